// round 4
// baseline (speedup 1.0000x reference)
#include <cuda_runtime.h>

#define Bb 2
#define Hh 8
#define Ll 4096
#define Dd 128
#define Cc 32
#define NCH 128          // chunks per sequence
#define BHh 16           // b*h
#define DVB 16           // dv columns per CTA in scan kernel
#define NDVB 8           // 128/16

#define ELEMS (BHh*Ll*Dd)          // 8388608
#define O_ELEMS ((size_t)ELEMS)    // offset of S in output

// Scratch (allocation-free requirement -> __device__ globals)
__device__ float g_qn[ELEMS];
__device__ float g_kn[ELEMS];
__device__ float g_w [ELEMS];
__device__ float g_u [ELEMS];
__device__ float g_att[BHh*NCH*Cc*Cc];

// ----------------------------------------------------------------------------
// Kernel 1: per-chunk preprocessing. grid = BHh*NCH (2048), block = 128
// ----------------------------------------------------------------------------
__global__ __launch_bounds__(128) void prep_kernel(
    const float* __restrict__ q, const float* __restrict__ k,
    const float* __restrict__ v, const float* __restrict__ beta)
{
    extern __shared__ float sm1[];
    float* sqT  = sm1;                 // [128][33]  q^T (normalized)
    float* skT  = sqT + 128*33;        // [128][33]  k^T (normalized)
    float* skb  = skT + 128*33;        // [32][128]  k_norm * beta (row-major)
    float* svb  = skb + 32*128;        // [32][128]  v * beta       (row-major)
    float* sA   = svb + 32*128;        // [32][33]   T matrix
    float* sbeta= sA  + 32*33;         // [32]

    const int tid  = threadIdx.x;
    const int lane = tid & 31;
    const int warp = tid >> 5;
    const int bh = blockIdx.x >> 7;    // / NCH
    const int ci = blockIdx.x & 127;   // % NCH
    const size_t base = ((size_t)bh*Ll + (size_t)ci*Cc)*Dd;

    // ---- load + l2-normalize q,k; scale v,k by beta ----
    for (int r = warp*8; r < warp*8 + 8; ++r) {
        float bet = beta[(size_t)bh*Ll + ci*Cc + r];
        const float4 xq = *(const float4*)(q + base + r*Dd + lane*4);
        const float4 xk = *(const float4*)(k + base + r*Dd + lane*4);
        const float4 xv = *(const float4*)(v + base + r*Dd + lane*4);
        float s2q = xq.x*xq.x + xq.y*xq.y + xq.z*xq.z + xq.w*xq.w;
        float s2k = xk.x*xk.x + xk.y*xk.y + xk.z*xk.z + xk.w*xk.w;
        #pragma unroll
        for (int o = 16; o; o >>= 1) {
            s2q += __shfl_xor_sync(0xffffffffu, s2q, o);
            s2k += __shfl_xor_sync(0xffffffffu, s2k, o);
        }
        float iq = rsqrtf(s2q + 1e-6f);
        float ik = rsqrtf(s2k + 1e-6f);
        float4 nq = make_float4(xq.x*iq, xq.y*iq, xq.z*iq, xq.w*iq);
        float4 nk = make_float4(xk.x*ik, xk.y*ik, xk.z*ik, xk.w*ik);
        *(float4*)(g_qn + base + r*Dd + lane*4) = nq;
        *(float4*)(g_kn + base + r*Dd + lane*4) = nk;
        const int d0 = lane*4;
        sqT[(d0+0)*33 + r] = nq.x; sqT[(d0+1)*33 + r] = nq.y;
        sqT[(d0+2)*33 + r] = nq.z; sqT[(d0+3)*33 + r] = nq.w;
        skT[(d0+0)*33 + r] = nk.x; skT[(d0+1)*33 + r] = nk.y;
        skT[(d0+2)*33 + r] = nk.z; skT[(d0+3)*33 + r] = nk.w;
        *(float4*)(skb + r*Dd + d0) = make_float4(nk.x*bet, nk.y*bet, nk.z*bet, nk.w*bet);
        *(float4*)(svb + r*Dd + d0) = make_float4(xv.x*bet, xv.y*bet, xv.z*bet, xv.w*bet);
        if (lane == 0) sbeta[r] = bet;
    }
    __syncthreads();

    // ---- Step B: A[i][j] = -beta_i * (kn_i . kn_j) for j<i, else 0 ----
    {
        const int i0 = (tid >> 3) * 2;
        const int j0 = (tid & 7) * 4;
        float a00=0.f,a01=0.f,a02=0.f,a03=0.f;
        float a10=0.f,a11=0.f,a12=0.f,a13=0.f;
        #pragma unroll 4
        for (int d = 0; d < Dd; ++d) {
            float ka0 = skT[d*33 + i0];
            float ka1 = skT[d*33 + i0 + 1];
            float b0  = skT[d*33 + j0];
            float b1  = skT[d*33 + j0 + 1];
            float b2  = skT[d*33 + j0 + 2];
            float b3  = skT[d*33 + j0 + 3];
            a00 += ka0*b0; a01 += ka0*b1; a02 += ka0*b2; a03 += ka0*b3;
            a10 += ka1*b0; a11 += ka1*b1; a12 += ka1*b2; a13 += ka1*b3;
        }
        float nb0 = -sbeta[i0], nb1 = -sbeta[i0+1];
        sA[(i0  )*33 + j0  ] = (j0   < i0  ) ? nb0*a00 : 0.f;
        sA[(i0  )*33 + j0+1] = (j0+1 < i0  ) ? nb0*a01 : 0.f;
        sA[(i0  )*33 + j0+2] = (j0+2 < i0  ) ? nb0*a02 : 0.f;
        sA[(i0  )*33 + j0+3] = (j0+3 < i0  ) ? nb0*a03 : 0.f;
        sA[(i0+1)*33 + j0  ] = (j0   < i0+1) ? nb1*a10 : 0.f;
        sA[(i0+1)*33 + j0+1] = (j0+1 < i0+1) ? nb1*a11 : 0.f;
        sA[(i0+1)*33 + j0+2] = (j0+2 < i0+1) ? nb1*a12 : 0.f;
        sA[(i0+1)*33 + j0+3] = (j0+3 < i0+1) ? nb1*a13 : 0.f;
    }
    __syncthreads();

    // ---- Step C: forward substitution (in-place), then += I. Warp 0 only ----
    if (warp == 0) {
        for (int i = 1; i < 32; ++i) {
            float rv  = sA[i*33 + lane];     // original row i
            float acc = rv;
            for (int j = 0; j < i; ++j)
                acc += __shfl_sync(0xffffffffu, rv, j) * sA[j*33 + lane];
            sA[i*33 + lane] = acc;
            __syncwarp();
        }
        sA[lane*33 + lane] += 1.0f;
    }
    __syncthreads();

    // ---- Step D: u = A @ (v*beta), w = A @ (kn*beta) ----
    {
        const int d = tid;                  // 0..127 column
        #pragma unroll
        for (int rb = 0; rb < 4; ++rb) {
            const int r0 = rb*8;
            float ar[8];
            #pragma unroll
            for (int rr = 0; rr < 8; ++rr) ar[rr] = sA[(r0+rr)*33 + lane];
            float au[8] = {0,0,0,0,0,0,0,0};
            float aw[8] = {0,0,0,0,0,0,0,0};
            for (int j = 0; j < 32; ++j) {
                float vb = svb[j*Dd + d];
                float kb = skb[j*Dd + d];
                #pragma unroll
                for (int rr = 0; rr < 8; ++rr) {
                    float a = __shfl_sync(0xffffffffu, ar[rr], j);
                    au[rr] += a*vb;
                    aw[rr] += a*kb;
                }
            }
            #pragma unroll
            for (int rr = 0; rr < 8; ++rr) {
                g_u[base + (size_t)(r0+rr)*Dd + d] = au[rr];
                g_w[base + (size_t)(r0+rr)*Dd + d] = aw[rr];
            }
        }
    }

    // ---- Step E: attn_local[i][j] = (j<=i) ? qn_i . kn_j : 0 ----
    {
        const int i0 = (tid >> 3) * 2;
        const int j0 = (tid & 7) * 4;
        float a00=0.f,a01=0.f,a02=0.f,a03=0.f;
        float a10=0.f,a11=0.f,a12=0.f,a13=0.f;
        #pragma unroll 4
        for (int d = 0; d < Dd; ++d) {
            float qa0 = sqT[d*33 + i0];
            float qa1 = sqT[d*33 + i0 + 1];
            float b0  = skT[d*33 + j0];
            float b1  = skT[d*33 + j0 + 1];
            float b2  = skT[d*33 + j0 + 2];
            float b3  = skT[d*33 + j0 + 3];
            a00 += qa0*b0; a01 += qa0*b1; a02 += qa0*b2; a03 += qa0*b3;
            a10 += qa1*b0; a11 += qa1*b1; a12 += qa1*b2; a13 += qa1*b3;
        }
        const size_t abase = ((size_t)bh*NCH + ci)*(Cc*Cc);
        g_att[abase + (i0  )*Cc + j0  ] = (j0   <= i0  ) ? a00 : 0.f;
        g_att[abase + (i0  )*Cc + j0+1] = (j0+1 <= i0  ) ? a01 : 0.f;
        g_att[abase + (i0  )*Cc + j0+2] = (j0+2 <= i0  ) ? a02 : 0.f;
        g_att[abase + (i0  )*Cc + j0+3] = (j0+3 <= i0  ) ? a03 : 0.f;
        g_att[abase + (i0+1)*Cc + j0  ] = (j0   <= i0+1) ? a10 : 0.f;
        g_att[abase + (i0+1)*Cc + j0+1] = (j0+1 <= i0+1) ? a11 : 0.f;
        g_att[abase + (i0+1)*Cc + j0+2] = (j0+2 <= i0+1) ? a12 : 0.f;
        g_att[abase + (i0+1)*Cc + j0+3] = (j0+3 <= i0+1) ? a13 : 0.f;
    }
}

// ----------------------------------------------------------------------------
// Kernel 2 (v2): sequential chunk scan. grid = (NDVB, BHh) = (8,16), block=512
// 16 warps; double-buffered register->smem prefetch; stride-129 staging.
// ----------------------------------------------------------------------------
#define XSTRIDE 129
#define SX_SZ (64*XSTRIDE)     // 8256
#define SK_SZ (32*XSTRIDE)     // 4128
#define SA_SZ (32*33)          // 1056
#define SU_SZ (32*16)          // 512

__global__ __launch_bounds__(512, 1) void scan_kernel(float* __restrict__ out)
{
    extern __shared__ float sm2[];
    float* sx  = sm2;                   // [2][64][129]  rows: 0-31 w, 32-63 qn
    float* sk  = sx  + 2*SX_SZ;         // [2][32][129]
    float* sA  = sk  + 2*SK_SZ;         // [2][32][33]
    float* su  = sA  + 2*SA_SZ;         // [2][32][16]
    float* sS  = su  + 2*SU_SZ;         // [128][16]
    float* su2 = sS  + 128*16;          // [32][16]
    float* sYp = su2 + 32*16;           // [2][64][16]  d-half partials

    const int cb = blockIdx.x;          // dv block
    const int bh = blockIdx.y;
    const int colbase = cb * DVB;
    const int tid  = threadIdx.x;
    const int lane = tid & 31;
    const int warp = tid >> 5;

    // Y-phase roles: 16 warps = 2 d-halves x 2 row-blocks x 4 col-groups
    const int dhalf  = warp >> 3;
    const int rowblk = (warp >> 2) & 1;
    const int colgrp = warp & 3;
    const int ym = rowblk*32 + lane;
    // S-update roles: 16 tiles of 32(d) x 4(c)
    const int s_d0 = (warp & 3)*32 + lane;
    const int s_c0 = (warp >> 2)*4;

    for (int i = tid; i < 128*16; i += 512) sS[i] = 0.f;

    // ---- prefetch registers ----
    float4 rx0, rx1, rx2, rx3, rk0, rk1, ru;
    float rA0, rA1;

    #define ISSUE_PREFETCH(ci) do {                                            \
        const size_t pbase = ((size_t)bh*Ll + (size_t)(ci)*Cc)*Dd;             \
        {                                                                      \
            int ch, m, d4; const float* src;                                   \
            ch = tid;          m = ch >> 5; d4 = ch & 31;                      \
            src = (m < 32) ? (g_w + pbase + (size_t)m*Dd)                      \
                           : (g_qn + pbase + (size_t)(m-32)*Dd);               \
            rx0 = *(const float4*)(src + d4*4);                                \
            ch = tid + 512;    m = ch >> 5; d4 = ch & 31;                      \
            src = (m < 32) ? (g_w + pbase + (size_t)m*Dd)                      \
                           : (g_qn + pbase + (size_t)(m-32)*Dd);               \
            rx1 = *(const float4*)(src + d4*4);                                \
            ch = tid + 1024;   m = ch >> 5; d4 = ch & 31;                      \
            src = (m < 32) ? (g_w + pbase + (size_t)m*Dd)                      \
                           : (g_qn + pbase + (size_t)(m-32)*Dd);               \
            rx2 = *(const float4*)(src + d4*4);                                \
            ch = tid + 1536;   m = ch >> 5; d4 = ch & 31;                      \
            src = (m < 32) ? (g_w + pbase + (size_t)m*Dd)                      \
                           : (g_qn + pbase + (size_t)(m-32)*Dd);               \
            rx3 = *(const float4*)(src + d4*4);                                \
            ch = tid;          m = ch >> 5; d4 = ch & 31;                      \
            rk0 = *(const float4*)(g_kn + pbase + (size_t)m*Dd + d4*4);        \
            ch = tid + 512;    m = ch >> 5; d4 = ch & 31;                      \
            rk1 = *(const float4*)(g_kn + pbase + (size_t)m*Dd + d4*4);        \
        }                                                                      \
        {                                                                      \
            const size_t abase = ((size_t)bh*NCH + (ci))*(Cc*Cc);              \
            rA0 = g_att[abase + tid*2];                                        \
            rA1 = g_att[abase + tid*2 + 1];                                    \
        }                                                                      \
        if (tid < 128) {                                                       \
            int r = tid >> 2, c4 = tid & 3;                                    \
            ru = *(const float4*)(g_u + pbase + (size_t)r*Dd + colbase + c4*4);\
        }                                                                      \
    } while (0)

    #define COMMIT(bufi) do {                                                  \
        float* dx = sx + (bufi)*SX_SZ;                                         \
        int ch, m, d0;                                                         \
        ch = tid;        m = ch >> 5; d0 = (ch & 31)*4;                        \
        dx[m*XSTRIDE+d0]=rx0.x; dx[m*XSTRIDE+d0+1]=rx0.y;                      \
        dx[m*XSTRIDE+d0+2]=rx0.z; dx[m*XSTRIDE+d0+3]=rx0.w;                    \
        ch = tid + 512;  m = ch >> 5; d0 = (ch & 31)*4;                        \
        dx[m*XSTRIDE+d0]=rx1.x; dx[m*XSTRIDE+d0+1]=rx1.y;                      \
        dx[m*XSTRIDE+d0+2]=rx1.z; dx[m*XSTRIDE+d0+3]=rx1.w;                    \
        ch = tid + 1024; m = ch >> 5; d0 = (ch & 31)*4;                        \
        dx[m*XSTRIDE+d0]=rx2.x; dx[m*XSTRIDE+d0+1]=rx2.y;                      \
        dx[m*XSTRIDE+d0+2]=rx2.z; dx[m*XSTRIDE+d0+3]=rx2.w;                    \
        ch = tid + 1536; m = ch >> 5; d0 = (ch & 31)*4;                        \
        dx[m*XSTRIDE+d0]=rx3.x; dx[m*XSTRIDE+d0+1]=rx3.y;                      \
        dx[m*XSTRIDE+d0+2]=rx3.z; dx[m*XSTRIDE+d0+3]=rx3.w;                    \
        float* dk = sk + (bufi)*SK_SZ;                                         \
        ch = tid;        m = ch >> 5; d0 = (ch & 31)*4;                        \
        dk[m*XSTRIDE+d0]=rk0.x; dk[m*XSTRIDE+d0+1]=rk0.y;                      \
        dk[m*XSTRIDE+d0+2]=rk0.z; dk[m*XSTRIDE+d0+3]=rk0.w;                    \
        ch = tid + 512;  m = ch >> 5; d0 = (ch & 31)*4;                        \
        dk[m*XSTRIDE+d0]=rk1.x; dk[m*XSTRIDE+d0+1]=rk1.y;                      \
        dk[m*XSTRIDE+d0+2]=rk1.z; dk[m*XSTRIDE+d0+3]=rk1.w;                    \
        float* dA = sA + (bufi)*SA_SZ;                                         \
        int i0 = tid*2;                                                        \
        dA[(i0>>5)*33 + (i0&31)] = rA0;                                        \
        i0++;                                                                  \
        dA[(i0>>5)*33 + (i0&31)] = rA1;                                        \
        if (tid < 128) {                                                       \
            int r = tid >> 2, c4 = tid & 3;                                    \
            *(float4*)(su + (bufi)*SU_SZ + r*16 + c4*4) = ru;                  \
        }                                                                      \
    } while (0)

    ISSUE_PREFETCH(0);
    COMMIT(0);
    __syncthreads();

    for (int ci = 0; ci < NCH; ++ci) {
        const int buf = ci & 1;
        const size_t base = ((size_t)bh*Ll + (size_t)ci*Cc)*Dd;

        if (ci + 1 < NCH) { ISSUE_PREFETCH(ci + 1); }

        // ---- Phase Y: partials of [w;q](64x128) @ S(128x16), d split in 2 ----
        {
            const float* xp = sx + buf*SX_SZ + ym*XSTRIDE + dhalf*64;
            const float* sp = sS + dhalf*64*16 + colgrp*4;
            float a0=0.f, a1=0.f, a2=0.f, a3=0.f;
            #pragma unroll 16
            for (int d = 0; d < 64; ++d) {
                float x = xp[d];
                float4 s = *(const float4*)(sp + d*16);
                a0 += x*s.x; a1 += x*s.y; a2 += x*s.z; a3 += x*s.w;
            }
            *(float4*)(sYp + dhalf*1024 + ym*16 + colgrp*4) =
                make_float4(a0, a1, a2, a3);
        }
        __syncthreads();

        // ---- Phase u': u' = u - (w@S)  (rows 0..31 of Y) ----
        if (tid < 128) {
            int r = tid >> 2, c4 = (tid & 3)*4;
            float4 uu = *(const float4*)(su + buf*SU_SZ + r*16 + c4);
            float4 p0 = *(const float4*)(sYp + r*16 + c4);
            float4 p1 = *(const float4*)(sYp + 1024 + r*16 + c4);
            *(float4*)(su2 + r*16 + c4) = make_float4(
                uu.x - p0.x - p1.x, uu.y - p0.y - p1.y,
                uu.z - p0.z - p1.z, uu.w - p0.w - p1.w);
        }
        __syncthreads();

        // ---- Phase 3a: S += k^T @ u'  (all 16 warps, 32x4 tiles) ----
        {
            const float* bk = sk + buf*SK_SZ;
            float4 acc = *(const float4*)(sS + s_d0*16 + s_c0);
            #pragma unroll 8
            for (int r = 0; r < 32; ++r) {
                float kk = bk[r*XSTRIDE + s_d0];
                float4 u4 = *(const float4*)(su2 + r*16 + s_c0);
                acc.x += kk*u4.x; acc.y += kk*u4.y;
                acc.z += kk*u4.z; acc.w += kk*u4.w;
            }
            *(float4*)(sS + s_d0*16 + s_c0) = acc;
        }

        // ---- Phase 3b: o = q@S + A@u'  (warps 0-3, 32x4 tiles) ----
        if (warp < 4) {
            const float* bA = sA + buf*SA_SZ;
            float a0=0.f, a1=0.f, a2=0.f, a3=0.f;
            #pragma unroll 8
            for (int j = 0; j < 32; ++j) {
                float a = bA[lane*33 + j];
                float4 u4 = *(const float4*)(su2 + j*16 + warp*4);
                a0 += a*u4.x; a1 += a*u4.y; a2 += a*u4.z; a3 += a*u4.w;
            }
            float4 p0 = *(const float4*)(sYp + (32+lane)*16 + warp*4);
            float4 p1 = *(const float4*)(sYp + 1024 + (32+lane)*16 + warp*4);
            *(float4*)&out[base + (size_t)lane*Dd + colbase + warp*4] =
                make_float4(a0 + p0.x + p1.x, a1 + p0.y + p1.y,
                            a2 + p0.z + p1.z, a3 + p0.w + p1.w);
        }

        // ---- commit next chunk's tiles to the other buffer ----
        if (ci + 1 < NCH) { COMMIT((ci + 1) & 1); }
        __syncthreads();
    }

    // ---- write final S ----
    for (int idx = tid; idx < 512; idx += 512) {
        int d = idx >> 2, c4 = (idx & 3)*4;
        *(float4*)&out[O_ELEMS + ((size_t)bh*Dd + d)*Dd + colbase + c4] =
            *(const float4*)(sS + d*16 + c4);
    }
}

// ----------------------------------------------------------------------------
extern "C" void kernel_launch(void* const* d_in, const int* in_sizes, int n_in,
                              void* d_out, int out_size)
{
    const float* q    = (const float*)d_in[0];
    const float* k    = (const float*)d_in[1];
    const float* v    = (const float*)d_in[2];
    const float* beta = (const float*)d_in[3];
    float* out = (float*)d_out;

    const int smem1 = (2*128*33 + 2*32*128 + 32*33 + 32) * 4;  // 70912 B
    const int smem2 = (2*SX_SZ + 2*SK_SZ + 2*SA_SZ + 2*SU_SZ
                       + 128*16 + 32*16 + 2*64*16) * 4;         // 130048 B
    cudaFuncSetAttribute(prep_kernel, cudaFuncAttributeMaxDynamicSharedMemorySize, smem1);
    cudaFuncSetAttribute(scan_kernel, cudaFuncAttributeMaxDynamicSharedMemorySize, smem2);

    prep_kernel<<<BHh*NCH, 128, smem1>>>(q, k, v, beta);
    scan_kernel<<<dim3(NDVB, BHh), 512, smem2>>>(out);
}

// round 6
// speedup vs baseline: 1.1062x; 1.1062x over previous
#include <cuda_runtime.h>

#define Ll 4096
#define Dd 128
#define Cc 32
#define NCH 128
#define BHh 16
#define DVB 16
#define NDVB 8
#define ELEMS (BHh*Ll*Dd)
#define O_ELEMS ((size_t)ELEMS)
#define NCHK (BHh*NCH)   // 2048 chunks total

// Scratch (__device__ globals; allocation-free rule)
__device__ float g_qn [ELEMS];            // q normalized, row-major (epilogue)
__device__ float g_u  [ELEMS];            // u = T(v*beta), row-major (scan)
__device__ float g_wT [NCHK*4096];        // per chunk: w^T [d][32] (scan)
__device__ float g_kT [NCHK*4096];        // per chunk: k^T [d][32] (scan)
__device__ float g_att[NCHK*1024];        // attn_local (epilogue)
__device__ float g_S  [(size_t)NCHK*16384]; // per chunk: S_i col-major [c][d]
__device__ float g_u2 [NCHK*4096];        // per chunk: u' col-major [c][r]

// ----------------------------------------------------------------------------
// Kernel 1: per-chunk preprocessing. grid = 2048, block = 128
// ----------------------------------------------------------------------------
__global__ __launch_bounds__(128) void prep_kernel(
    const float* __restrict__ q, const float* __restrict__ k,
    const float* __restrict__ v, const float* __restrict__ beta)
{
    extern __shared__ float sm1[];
    float* sqT   = sm1;                // [128][33]
    float* skT   = sqT + 4224;         // [128][33]
    float* svb   = skT + 4224;         // [32][128]
    float* sA    = svb + 4096;         // [32][33]
    float* sbeta = sA  + 1056;         // [32]

    const int tid  = threadIdx.x;
    const int lane = tid & 31;
    const int warp = tid >> 5;
    const int bh = blockIdx.x >> 7;
    const int ci = blockIdx.x & 127;
    const int chk = blockIdx.x;
    const size_t base = ((size_t)bh*Ll + (size_t)ci*Cc)*Dd;

    for (int r = warp*8; r < warp*8 + 8; ++r) {
        float bet = beta[(size_t)bh*Ll + ci*Cc + r];
        const float4 xq = *(const float4*)(q + base + r*Dd + lane*4);
        const float4 xk = *(const float4*)(k + base + r*Dd + lane*4);
        const float4 xv = *(const float4*)(v + base + r*Dd + lane*4);
        float s2q = xq.x*xq.x + xq.y*xq.y + xq.z*xq.z + xq.w*xq.w;
        float s2k = xk.x*xk.x + xk.y*xk.y + xk.z*xk.z + xk.w*xk.w;
        #pragma unroll
        for (int o = 16; o; o >>= 1) {
            s2q += __shfl_xor_sync(0xffffffffu, s2q, o);
            s2k += __shfl_xor_sync(0xffffffffu, s2k, o);
        }
        float iq = rsqrtf(s2q + 1e-6f);
        float ik = rsqrtf(s2k + 1e-6f);
        float4 nq = make_float4(xq.x*iq, xq.y*iq, xq.z*iq, xq.w*iq);
        float4 nk = make_float4(xk.x*ik, xk.y*ik, xk.z*ik, xk.w*ik);
        *(float4*)(g_qn + base + r*Dd + lane*4) = nq;
        const int d0 = lane*4;
        sqT[(d0+0)*33 + r] = nq.x; sqT[(d0+1)*33 + r] = nq.y;
        sqT[(d0+2)*33 + r] = nq.z; sqT[(d0+3)*33 + r] = nq.w;
        skT[(d0+0)*33 + r] = nk.x; skT[(d0+1)*33 + r] = nk.y;
        skT[(d0+2)*33 + r] = nk.z; skT[(d0+3)*33 + r] = nk.w;
        *(float4*)(svb + r*Dd + d0) = make_float4(xv.x*bet, xv.y*bet, xv.z*bet, xv.w*bet);
        if (lane == 0) sbeta[r] = bet;
    }
    __syncthreads();

    // write k^T [d][32] for scan
    {
        const int d = tid;
        #pragma unroll
        for (int r4 = 0; r4 < 32; r4 += 4) {
            *(float4*)&g_kT[(size_t)chk*4096 + d*32 + r4] = make_float4(
                skT[d*33+r4], skT[d*33+r4+1], skT[d*33+r4+2], skT[d*33+r4+3]);
        }
    }

    // A = -beta_i (k_i.k_j) strict-lower ; E = q_i.k_j incl-lower -> g_att
    {
        const int i0 = (tid >> 3) * 2;
        const int j0 = (tid & 7) * 4;
        float a00=0,a01=0,a02=0,a03=0,a10=0,a11=0,a12=0,a13=0;
        float e00=0,e01=0,e02=0,e03=0,e10=0,e11=0,e12=0,e13=0;
        #pragma unroll 4
        for (int d = 0; d < Dd; ++d) {
            const float* kc = skT + d*33;
            const float* qc = sqT + d*33;
            float b0=kc[j0], b1=kc[j0+1], b2=kc[j0+2], b3=kc[j0+3];
            float ka0=kc[i0], ka1=kc[i0+1], qa0=qc[i0], qa1=qc[i0+1];
            a00+=ka0*b0; a01+=ka0*b1; a02+=ka0*b2; a03+=ka0*b3;
            a10+=ka1*b0; a11+=ka1*b1; a12+=ka1*b2; a13+=ka1*b3;
            e00+=qa0*b0; e01+=qa0*b1; e02+=qa0*b2; e03+=qa0*b3;
            e10+=qa1*b0; e11+=qa1*b1; e12+=qa1*b2; e13+=qa1*b3;
        }
        float nb0 = -sbeta[i0], nb1 = -sbeta[i0+1];
        sA[(i0  )*33+j0  ] = (j0  <i0  ) ? nb0*a00 : 0.f;
        sA[(i0  )*33+j0+1] = (j0+1<i0  ) ? nb0*a01 : 0.f;
        sA[(i0  )*33+j0+2] = (j0+2<i0  ) ? nb0*a02 : 0.f;
        sA[(i0  )*33+j0+3] = (j0+3<i0  ) ? nb0*a03 : 0.f;
        sA[(i0+1)*33+j0  ] = (j0  <i0+1) ? nb1*a10 : 0.f;
        sA[(i0+1)*33+j0+1] = (j0+1<i0+1) ? nb1*a11 : 0.f;
        sA[(i0+1)*33+j0+2] = (j0+2<i0+1) ? nb1*a12 : 0.f;
        sA[(i0+1)*33+j0+3] = (j0+3<i0+1) ? nb1*a13 : 0.f;
        float* ga = g_att + (size_t)chk*1024;
        ga[(i0  )*Cc+j0  ] = (j0  <=i0  ) ? e00 : 0.f;
        ga[(i0  )*Cc+j0+1] = (j0+1<=i0  ) ? e01 : 0.f;
        ga[(i0  )*Cc+j0+2] = (j0+2<=i0  ) ? e02 : 0.f;
        ga[(i0  )*Cc+j0+3] = (j0+3<=i0  ) ? e03 : 0.f;
        ga[(i0+1)*Cc+j0  ] = (j0  <=i0+1) ? e10 : 0.f;
        ga[(i0+1)*Cc+j0+1] = (j0+1<=i0+1) ? e11 : 0.f;
        ga[(i0+1)*Cc+j0+2] = (j0+2<=i0+1) ? e12 : 0.f;
        ga[(i0+1)*Cc+j0+3] = (j0+3<=i0+1) ? e13 : 0.f;
    }
    __syncthreads();

    // forward substitution (warp 0), then += I
    if (warp == 0) {
        for (int i = 1; i < 32; ++i) {
            float rv  = sA[i*33 + lane];
            float acc = rv;
            for (int j = 0; j < i; ++j)
                acc += __shfl_sync(0xffffffffu, rv, j) * sA[j*33 + lane];
            sA[i*33 + lane] = acc;
            __syncwarp();
        }
        sA[lane*33 + lane] += 1.0f;
    }
    __syncthreads();

    // u = T(v*beta) row-major ; w = T(k*beta) -> g_wT transposed
    {
        const int d = tid;
        #pragma unroll
        for (int rb = 0; rb < 4; ++rb) {
            const int r0 = rb*8;
            float ar[8];
            #pragma unroll
            for (int rr = 0; rr < 8; ++rr) ar[rr] = sA[(r0+rr)*33 + lane];
            float au[8] = {0,0,0,0,0,0,0,0};
            float aw[8] = {0,0,0,0,0,0,0,0};
            for (int j = 0; j < 32; ++j) {
                float vb = svb[j*Dd + d];
                float kb = skT[d*33 + j] * sbeta[j];
                #pragma unroll
                for (int rr = 0; rr < 8; ++rr) {
                    float a = __shfl_sync(0xffffffffu, ar[rr], j);
                    au[rr] += a*vb;
                    aw[rr] += a*kb;
                }
            }
            #pragma unroll
            for (int rr = 0; rr < 8; ++rr)
                g_u[base + (size_t)(r0+rr)*Dd + d] = au[rr];
            *(float4*)&g_wT[(size_t)chk*4096 + d*32 + r0    ] = make_float4(aw[0],aw[1],aw[2],aw[3]);
            *(float4*)&g_wT[(size_t)chk*4096 + d*32 + r0 + 4] = make_float4(aw[4],aw[5],aw[6],aw[7]);
        }
    }
}

// ----------------------------------------------------------------------------
// Kernel 2: sequential scan (state only). grid = (8,16), block = 512.
// ----------------------------------------------------------------------------
#define WST 36
#define KST 33
#define SST 20
#define SW_SZ (128*WST)   // 4608
#define SK_SZ (128*KST)   // 4224

__global__ __launch_bounds__(512, 1) void scan_kernel(float* __restrict__ out)
{
    extern __shared__ float sm2[];
    float* swT = sm2;                   // [2][128][36]
    float* skT = swT + 2*SW_SZ;         // [2][128][33]
    float* sS  = skT + 2*SK_SZ;         // [128][20]
    float* sYp = sS  + 2560;            // [8][32][20]
    float* su2 = sYp + 5120;            // [32][20]

    const int cb = blockIdx.x;
    const int bh = blockIdx.y;
    const int colbase = cb * DVB;
    const int tid  = threadIdx.x;
    const int lane = tid & 31;
    const int warp = tid >> 5;

    const int dq  = warp >> 1;
    const int cg8 = (warp & 1) * 8;
    const int udq = warp >> 2;
    const int ucg = warp & 3;
    const int sd  = udq*32 + lane;
    const int tw4 = (tid >> 5) * 4;

    const int cd = tid >> 2;
    const int cr = (tid & 3) * 8;

    float4 Sreg = make_float4(0.f, 0.f, 0.f, 0.f);
    for (int i = tid; i < 2560; i += 512) sS[i] = 0.f;

    float4 rw0, rw1, rk0, rk1, ru;

    {
        const size_t tb = ((size_t)(bh*NCH))*4096;
        rw0 = *(const float4*)(g_wT + tb + tid*8);
        rw1 = *(const float4*)(g_wT + tb + tid*8 + 4);
        rk0 = *(const float4*)(g_kT + tb + tid*8);
        rk1 = *(const float4*)(g_kT + tb + tid*8 + 4);
        if (tid < 128)
            ru = *(const float4*)(g_u + ((size_t)bh*Ll + (tid&31))*Dd + colbase + tw4);
    }
    {
        *(float4*)&swT[cd*WST + cr    ] = rw0;
        *(float4*)&swT[cd*WST + cr + 4] = rw1;
        skT[cd*KST+cr  ]=rk0.x; skT[cd*KST+cr+1]=rk0.y;
        skT[cd*KST+cr+2]=rk0.z; skT[cd*KST+cr+3]=rk0.w;
        skT[cd*KST+cr+4]=rk1.x; skT[cd*KST+cr+5]=rk1.y;
        skT[cd*KST+cr+6]=rk1.z; skT[cd*KST+cr+7]=rk1.w;
    }
    __syncthreads();

    for (int ci = 0; ci < NCH; ++ci) {
        const int buf = ci & 1;
        const int chk = bh*NCH + ci;

        // persist S_i (pre-chunk state), col-major [c][d]
        {
            float* gs = g_S + (size_t)chk*16384 + (size_t)(colbase + ucg*4)*128 + sd;
            gs[0] = Sreg.x; gs[128] = Sreg.y; gs[256] = Sreg.z; gs[384] = Sreg.w;
        }
        float4 ru_next = ru;
        if (ci + 1 < NCH) {
            const size_t tb = ((size_t)(chk+1))*4096;
            rw0 = *(const float4*)(g_wT + tb + tid*8);
            rw1 = *(const float4*)(g_wT + tb + tid*8 + 4);
            rk0 = *(const float4*)(g_kT + tb + tid*8);
            rk1 = *(const float4*)(g_kT + tb + tid*8 + 4);
            if (tid < 128)
                ru_next = *(const float4*)(g_u + ((size_t)bh*Ll + (size_t)(ci+1)*Cc + (tid&31))*Dd + colbase + tw4);
        }

        // Y: partial of w(32x128) @ S(128x16)
        {
            const float* xw = swT + buf*SW_SZ;
            float4 y0 = make_float4(0,0,0,0), y1 = make_float4(0,0,0,0);
            #pragma unroll
            for (int j = 0; j < 16; ++j) {
                const int jd = dq*16 + j;
                float x = xw[jd*WST + lane];
                float4 s0 = *(const float4*)&sS[jd*SST + cg8];
                float4 s1 = *(const float4*)&sS[jd*SST + cg8 + 4];
                y0.x += x*s0.x; y0.y += x*s0.y; y0.z += x*s0.z; y0.w += x*s0.w;
                y1.x += x*s1.x; y1.y += x*s1.y; y1.z += x*s1.z; y1.w += x*s1.w;
            }
            *(float4*)&sYp[dq*640 + lane*SST + cg8    ] = y0;
            *(float4*)&sYp[dq*640 + lane*SST + cg8 + 4] = y1;
        }
        __syncthreads();

        // u' = u - w@S
        if (tid < 128) {
            const int r = lane;
            float4 acc = ru;
            #pragma unroll
            for (int d8 = 0; d8 < 8; ++d8) {
                float4 p = *(const float4*)&sYp[d8*640 + r*SST + tw4];
                acc.x -= p.x; acc.y -= p.y; acc.z -= p.z; acc.w -= p.w;
            }
            *(float4*)&su2[r*SST + tw4] = acc;
            float* gu = g_u2 + (size_t)chk*4096 + (colbase + tw4)*32 + r;
            gu[0] = acc.x; gu[32] = acc.y; gu[64] = acc.z; gu[96] = acc.w;
        }
        __syncthreads();

        // S += k^T @ u'
        {
            const float* kp = skT + buf*SK_SZ + sd*KST;
            #pragma unroll 8
            for (int r = 0; r < 32; ++r) {
                float kk = kp[r];
                float4 u4 = *(const float4*)&su2[r*SST + ucg*4];
                Sreg.x += kk*u4.x; Sreg.y += kk*u4.y;
                Sreg.z += kk*u4.z; Sreg.w += kk*u4.w;
            }
            *(float4*)&sS[sd*SST + ucg*4] = Sreg;
        }
        if (ci + 1 < NCH) {
            const int b2 = (ci+1) & 1;
            float* dw = swT + b2*SW_SZ;
            float* dk = skT + b2*SK_SZ;
            *(float4*)&dw[cd*WST + cr    ] = rw0;
            *(float4*)&dw[cd*WST + cr + 4] = rw1;
            dk[cd*KST+cr  ]=rk0.x; dk[cd*KST+cr+1]=rk0.y;
            dk[cd*KST+cr+2]=rk0.z; dk[cd*KST+cr+3]=rk0.w;
            dk[cd*KST+cr+4]=rk1.x; dk[cd*KST+cr+5]=rk1.y;
            dk[cd*KST+cr+6]=rk1.z; dk[cd*KST+cr+7]=rk1.w;
            ru = ru_next;
        }
        __syncthreads();
    }

    *(float4*)&out[O_ELEMS + ((size_t)bh*Dd + sd)*Dd + colbase + ucg*4] = Sreg;
}

// ----------------------------------------------------------------------------
// Kernel 3: epilogue o = q@S_i + A@u'_i. grid = (NCH, BHh), block = 256.
// ----------------------------------------------------------------------------
#define AST 36

__global__ __launch_bounds__(256) void epi_kernel(float* __restrict__ out)
{
    extern __shared__ float sm3[];
    float* sS = sm3;              // [128][132] row-major S
    float* sq = sS + 128*132;     // [32][132]
    float* su = sq + 32*132;      // [32][132]
    float* sA = su + 32*132;      // [32][36]

    const int ci = blockIdx.x;
    const int bh = blockIdx.y;
    const int chk = bh*NCH + ci;
    const int tid = threadIdx.x;
    const size_t qbase = ((size_t)bh*Ll + (size_t)ci*Cc)*Dd;

    // stage S (col-major gmem -> row-major smem)
    {
        const int c = tid >> 1;
        const int db = (tid & 1) * 64;
        const float* gs = g_S + (size_t)chk*16384 + (size_t)c*128 + db;
        #pragma unroll
        for (int i = 0; i < 16; ++i) {
            float4 f = *(const float4*)(gs + i*4);
            int d = db + i*4;
            sS[(d  )*132 + c] = f.x; sS[(d+1)*132 + c] = f.y;
            sS[(d+2)*132 + c] = f.z; sS[(d+3)*132 + c] = f.w;
        }
    }
    // stage q (row-major)
    {
        #pragma unroll
        for (int t = 0; t < 4; ++t) {
            int i4 = (tid + t*256) * 4;
            float4 f = *(const float4*)(g_qn + qbase + i4);
            *(float4*)&sq[(i4 >> 7)*132 + (i4 & 127)] = f;
        }
    }
    // stage u' (col-major gmem -> row-major smem)
    {
        #pragma unroll
        for (int t = 0; t < 4; ++t) {
            int i4 = (tid + t*256) * 4;        // c = i4>>5, r = i4&31
            float4 f = *(const float4*)(g_u2 + (size_t)chk*4096 + i4);
            int c = i4 >> 5, r = i4 & 31;
            su[(r  )*132 + c] = f.x; su[(r+1)*132 + c] = f.y;
            su[(r+2)*132 + c] = f.z; su[(r+3)*132 + c] = f.w;
        }
    }
    // stage A (stride 36: 16B-aligned float4 rows)
    {
        int i4 = tid * 4;
        float4 f = *(const float4*)(g_att + (size_t)chk*1024 + i4);
        *(float4*)&sA[(i4 >> 5)*AST + (i4 & 31)] = f;
    }
    __syncthreads();

    // compute: thread tile 2 rows x 8 cols
    const int m0 = (tid >> 4) * 2;
    const int m1 = m0 + 1;
    const int cbk = (tid & 15) * 8;
    float4 a00 = make_float4(0,0,0,0), a01 = a00, a10 = a00, a11 = a00;
    #pragma unroll 8
    for (int d = 0; d < 128; ++d) {
        float q0 = sq[m0*132 + d];
        float q1 = sq[m1*132 + d];
        float4 s0 = *(const float4*)&sS[d*132 + cbk];
        float4 s1 = *(const float4*)&sS[d*132 + cbk + 4];
        a00.x += q0*s0.x; a00.y += q0*s0.y; a00.z += q0*s0.z; a00.w += q0*s0.w;
        a01.x += q0*s1.x; a01.y += q0*s1.y; a01.z += q0*s1.z; a01.w += q0*s1.w;
        a10.x += q1*s0.x; a10.y += q1*s0.y; a10.z += q1*s0.z; a10.w += q1*s0.w;
        a11.x += q1*s1.x; a11.y += q1*s1.y; a11.z += q1*s1.z; a11.w += q1*s1.w;
    }
    #pragma unroll 8
    for (int j = 0; j < 32; ++j) {
        float p0 = sA[m0*AST + j];
        float p1 = sA[m1*AST + j];
        float4 u0 = *(const float4*)&su[j*132 + cbk];
        float4 u1 = *(const float4*)&su[j*132 + cbk + 4];
        a00.x += p0*u0.x; a00.y += p0*u0.y; a00.z += p0*u0.z; a00.w += p0*u0.w;
        a01.x += p0*u1.x; a01.y += p0*u1.y; a01.z += p0*u1.z; a01.w += p0*u1.w;
        a10.x += p1*u0.x; a10.y += p1*u0.y; a10.z += p1*u0.z; a10.w += p1*u0.w;
        a11.x += p1*u1.x; a11.y += p1*u1.y; a11.z += p1*u1.z; a11.w += p1*u1.w;
    }
    float* o0 = out + qbase + (size_t)m0*Dd + cbk;
    float* o1 = out + qbase + (size_t)m1*Dd + cbk;
    *(float4*)(o0)     = a00; *(float4*)(o0 + 4) = a01;
    *(float4*)(o1)     = a10; *(float4*)(o1 + 4) = a11;
}

// ----------------------------------------------------------------------------
extern "C" void kernel_launch(void* const* d_in, const int* in_sizes, int n_in,
                              void* d_out, int out_size)
{
    const float* q    = (const float*)d_in[0];
    const float* k    = (const float*)d_in[1];
    const float* v    = (const float*)d_in[2];
    const float* beta = (const float*)d_in[3];
    float* out = (float*)d_out;

    const int smem1 = (2*4224 + 4096 + 1056 + 32) * 4;                 // 54528
    const int smem2 = (2*SW_SZ + 2*SK_SZ + 2560 + 5120 + 640) * 4;     // 103936
    const int smem3 = (128*132 + 32*132 + 32*132 + 32*AST) * 4;        // 105984
    cudaFuncSetAttribute(prep_kernel, cudaFuncAttributeMaxDynamicSharedMemorySize, smem1);
    cudaFuncSetAttribute(scan_kernel, cudaFuncAttributeMaxDynamicSharedMemorySize, smem2);
    cudaFuncSetAttribute(epi_kernel,  cudaFuncAttributeMaxDynamicSharedMemorySize, smem3);

    prep_kernel<<<NCHK, 128, smem1>>>(q, k, v, beta);
    scan_kernel<<<dim3(NDVB, BHh), 512, smem2>>>(out);
    epi_kernel<<<dim3(NCH, BHh), 256, smem3>>>(out);
}